// round 2
// baseline (speedup 1.0000x reference)
#include <cuda_runtime.h>
#include <math.h>

// Problem constants (fixed shapes for this problem instance)
#define V_SIZE    10000
#define NV4       2500          // V_SIZE / 4
#define N_EXPERTS 8
#define TOPK      2
#define THREADS   256

// ---------------------------------------------------------------------------
// Zero the output scalar (d_out is poisoned to 0xAA by the harness).
// ---------------------------------------------------------------------------
__global__ void zero_out_kernel(float* out) { out[0] = 0.0f; }

// ---------------------------------------------------------------------------
// Label-smoothing loss: one CTA per row of x (10000 f32 = 40 KB contiguous).
// Online softmax per thread (conditional rescale: ~1 MUFU exp per element),
// shared-memory tree combine of (max, sumexp, sum), then per-row KL term
// atomically accumulated into the scalar.
// ---------------------------------------------------------------------------
__global__ __launch_bounds__(THREADS)
void row_kernel(const float* __restrict__ x,
                const int* __restrict__ target,
                float* __restrict__ out,
                float inv_denom)
{
    const int row = blockIdx.x;
    const int t   = threadIdx.x;

    const int tgt = target[row];
    const bool ignore = (tgt < 0);   // PADDING_IDX = -1

    const float4* __restrict__ xr =
        reinterpret_cast<const float4*>(x + (size_t)row * V_SIZE);

    // Target logit (thread 0 only; single L2-warm load)
    float xt = 0.0f;
    if (t == 0 && !ignore) {
        xt = __ldg(x + (size_t)row * V_SIZE + (size_t)tgt);
    }

    // Per-thread online softmax over strided float4s (streaming loads).
    float m  = -3.402823466e38f;
    float s  = 0.0f;
    float sx = 0.0f;

    for (int i = t; i < NV4; i += THREADS) {
        float4 v = __ldcs(&xr[i]);
        {
            float c = v.x; sx += c;
            if (c > m) { s *= __expf(m - c); m = c; }
            s += __expf(c - m);
        }
        {
            float c = v.y; sx += c;
            if (c > m) { s *= __expf(m - c); m = c; }
            s += __expf(c - m);
        }
        {
            float c = v.z; sx += c;
            if (c > m) { s *= __expf(m - c); m = c; }
            s += __expf(c - m);
        }
        {
            float c = v.w; sx += c;
            if (c > m) { s *= __expf(m - c); m = c; }
            s += __expf(c - m);
        }
    }

    // Block combine. Every thread processed >= 9 elements, so m is finite.
    __shared__ float red_m[THREADS];
    __shared__ float red_s[THREADS];
    __shared__ float red_x[THREADS];
    red_m[t] = m; red_s[t] = s; red_x[t] = sx;
    __syncthreads();

    #pragma unroll
    for (int off = THREADS / 2; off > 0; off >>= 1) {
        if (t < off) {
            float m1 = red_m[t],       s1 = red_s[t];
            float m2 = red_m[t + off], s2 = red_s[t + off];
            float M  = fmaxf(m1, m2);
            red_s[t] = s1 * __expf(m1 - M) + s2 * __expf(m2 - M);
            red_m[t] = M;
            red_x[t] += red_x[t + off];
        }
        __syncthreads();
    }

    if (t == 0 && !ignore) {
        const float lse      = red_m[0] + logf(red_s[0]);
        const float sum_logp = red_x[0] - (float)V_SIZE * lse;
        const float logp_tgt = xt - lse;

        const float smooth = 0.1f / (float)(V_SIZE - 1);
        const float conf   = 0.9f;
        // Constant entropy term, folded at compile time (double precision).
        const double smooth_d = 0.1 / (double)(V_SIZE - 1);
        const float ent = (float)((double)(V_SIZE - 1) * smooth_d * log(smooth_d)
                                  + 0.9 * log(0.9));

        const float cross  = smooth * (sum_logp - logp_tgt) + conf * logp_tgt;
        const float kl_row = ent - cross;

        atomicAdd(out, kl_row * inv_denom);
    }
}

// ---------------------------------------------------------------------------
// z-loss: mean over rows of logsumexp(gate_logits)^2, both local and global.
// One thread per row (8 logits per row).
// ---------------------------------------------------------------------------
__global__ __launch_bounds__(THREADS)
void z_kernel(const float* __restrict__ gl_local,
              const float* __restrict__ gl_global,
              float* __restrict__ out,
              int N, float coef)   // coef = Z_COEF * 0.5 / N
{
    const int i = blockIdx.x * THREADS + threadIdx.x;
    float val = 0.0f;

    if (i < 2 * N) {
        const float* g = (i < N) ? (gl_local  + (size_t)i       * N_EXPERTS)
                                 : (gl_global + (size_t)(i - N) * N_EXPERTS);
        float m = g[0];
        #pragma unroll
        for (int j = 1; j < N_EXPERTS; j++) m = fmaxf(m, g[j]);
        float s = 0.0f;
        #pragma unroll
        for (int j = 0; j < N_EXPERTS; j++) s += __expf(g[j] - m);
        const float lse = m + logf(s);
        val = lse * lse;
    }

    __shared__ float red[THREADS];
    red[threadIdx.x] = val;
    __syncthreads();
    #pragma unroll
    for (int off = THREADS / 2; off > 0; off >>= 1) {
        if (threadIdx.x < off) red[threadIdx.x] += red[threadIdx.x + off];
        __syncthreads();
    }
    if (threadIdx.x == 0) atomicAdd(out, red[0] * coef);
}

// ---------------------------------------------------------------------------
// Load-balance loss. Block 0 = local, block 1 = global. Per-thread register
// histograms over the 8 experts, combined via shared atomics.
// ---------------------------------------------------------------------------
__global__ __launch_bounds__(THREADS)
void lb_kernel(const float* __restrict__ tv_l, const int* __restrict__ ti_l,
               const float* __restrict__ tv_g, const int* __restrict__ ti_g,
               float* __restrict__ out,
               int N, float coef)  // coef = LB_COEF * 0.5 * N_EXPERTS / N
{
    const float* tv = blockIdx.x ? tv_g : tv_l;
    const int*   ti = blockIdx.x ? ti_g : ti_l;
    const int total = N * TOPK;

    float cnt[N_EXPERTS];
    float sm [N_EXPERTS];
    #pragma unroll
    for (int j = 0; j < N_EXPERTS; j++) { cnt[j] = 0.0f; sm[j] = 0.0f; }

    for (int i = threadIdx.x; i < total; i += THREADS) {
        const int   e = ti[i];
        const float v = tv[i];
        #pragma unroll
        for (int j = 0; j < N_EXPERTS; j++) {
            const bool hit = (e == j);
            cnt[j] += hit ? 1.0f : 0.0f;
            sm[j]  += hit ? v    : 0.0f;
        }
    }

    __shared__ float s_cnt[N_EXPERTS];
    __shared__ float s_sm [N_EXPERTS];
    if (threadIdx.x < N_EXPERTS) { s_cnt[threadIdx.x] = 0.0f; s_sm[threadIdx.x] = 0.0f; }
    __syncthreads();
    #pragma unroll
    for (int j = 0; j < N_EXPERTS; j++) {
        atomicAdd(&s_cnt[j], cnt[j]);
        atomicAdd(&s_sm [j], sm[j]);
    }
    __syncthreads();

    if (threadIdx.x == 0) {
        float acc = 0.0f;
        #pragma unroll
        for (int j = 0; j < N_EXPERTS; j++) acc += s_cnt[j] * s_sm[j];
        atomicAdd(out, acc * coef);
    }
}

// ---------------------------------------------------------------------------
// Launch
// ---------------------------------------------------------------------------
extern "C" void kernel_launch(void* const* d_in, const int* in_sizes, int n_in,
                              void* d_out, int out_size)
{
    const float* x    = (const float*)d_in[0];
    const int*   tgt  = (const int*)  d_in[1];
    const float* tv_l = (const float*)d_in[2];
    const int*   ti_l = (const int*)  d_in[3];
    const float* gl_l = (const float*)d_in[4];
    const float* tv_g = (const float*)d_in[5];
    const int*   ti_g = (const int*)  d_in[6];
    const float* gl_g = (const float*)d_in[7];

    float* out = (float*)d_out;

    const int N = in_sizes[1];          // B*T = 8192
    const int B = N / 1024;             // batch = 8 (denominator, NORMALIZE_LENGTH=false)

    zero_out_kernel<<<1, 1>>>(out);

    row_kernel<<<N, THREADS>>>(x, tgt, out, 1.0f / (float)B);

    const int zblocks = (2 * N + THREADS - 1) / THREADS;
    z_kernel<<<zblocks, THREADS>>>(gl_l, gl_g, out, N, 0.001f * 0.5f / (float)N);

    lb_kernel<<<2, THREADS>>>(tv_l, ti_l, tv_g, ti_g, out, N,
                              0.01f * 0.5f * (float)N_EXPERTS / (float)N);
}

// round 4
// speedup vs baseline: 1.2628x; 1.2628x over previous
#include <cuda_runtime.h>
#include <math.h>

// Problem constants (fixed shapes for this problem instance)
#define V_SIZE    10000
#define NV4       2500          // V_SIZE / 4
#define N_EXPERTS 8
#define TOPK      2
#define THREADS   256
#define LB_BLOCKS_PER_SIDE 32

// Scratch for the load-balance partial sums: [side][expert]
__device__ float g_lb_cnt[2 * N_EXPERTS];
__device__ float g_lb_sum[2 * N_EXPERTS];

// ---------------------------------------------------------------------------
// Zero the output scalar and load-balance scratch.
// ---------------------------------------------------------------------------
__global__ void zero_out_kernel(float* out)
{
    if (threadIdx.x == 0) out[0] = 0.0f;
    if (threadIdx.x < 2 * N_EXPERTS) {
        g_lb_cnt[threadIdx.x] = 0.0f;
        g_lb_sum[threadIdx.x] = 0.0f;
    }
}

// ---------------------------------------------------------------------------
// Label-smoothing loss: one CTA per row of x (10000 f32 = 40 KB contiguous).
// Online softmax per thread (conditional rescale: ~1 MUFU exp per element),
// shared-memory tree combine of (max, sumexp, sum), then per-row KL term
// atomically accumulated into the scalar.
// ---------------------------------------------------------------------------
__global__ __launch_bounds__(THREADS)
void row_kernel(const float* __restrict__ x,
                const int* __restrict__ target,
                float* __restrict__ out,
                float inv_denom)
{
    const int row = blockIdx.x;
    const int t   = threadIdx.x;

    const int tgt = target[row];
    const bool ignore = (tgt < 0);   // PADDING_IDX = -1

    const float4* __restrict__ xr =
        reinterpret_cast<const float4*>(x + (size_t)row * V_SIZE);

    // Target logit (thread 0 only; single L2-warm load)
    float xt = 0.0f;
    if (t == 0 && !ignore) {
        xt = __ldg(x + (size_t)row * V_SIZE + (size_t)tgt);
    }

    // Per-thread online softmax over strided float4s (streaming loads).
    float m  = -3.402823466e38f;
    float s  = 0.0f;
    float sx = 0.0f;

    for (int i = t; i < NV4; i += THREADS) {
        float4 v = __ldcs(&xr[i]);
        {
            float c = v.x; sx += c;
            if (c > m) { s *= __expf(m - c); m = c; }
            s += __expf(c - m);
        }
        {
            float c = v.y; sx += c;
            if (c > m) { s *= __expf(m - c); m = c; }
            s += __expf(c - m);
        }
        {
            float c = v.z; sx += c;
            if (c > m) { s *= __expf(m - c); m = c; }
            s += __expf(c - m);
        }
        {
            float c = v.w; sx += c;
            if (c > m) { s *= __expf(m - c); m = c; }
            s += __expf(c - m);
        }
    }

    // Block combine. Every thread processed >= 9 elements, so m is finite.
    __shared__ float red_m[THREADS];
    __shared__ float red_s[THREADS];
    __shared__ float red_x[THREADS];
    red_m[t] = m; red_s[t] = s; red_x[t] = sx;
    __syncthreads();

    #pragma unroll
    for (int off = THREADS / 2; off > 0; off >>= 1) {
        if (t < off) {
            float m1 = red_m[t],       s1 = red_s[t];
            float m2 = red_m[t + off], s2 = red_s[t + off];
            float M  = fmaxf(m1, m2);
            red_s[t] = s1 * __expf(m1 - M) + s2 * __expf(m2 - M);
            red_m[t] = M;
            red_x[t] += red_x[t + off];
        }
        __syncthreads();
    }

    if (t == 0 && !ignore) {
        const float lse      = red_m[0] + logf(red_s[0]);
        const float sum_logp = red_x[0] - (float)V_SIZE * lse;
        const float logp_tgt = xt - lse;

        const float smooth = 0.1f / (float)(V_SIZE - 1);
        const float conf   = 0.9f;
        // Constant entropy term, folded at compile time (double precision).
        const double smooth_d = 0.1 / (double)(V_SIZE - 1);
        const float ent = (float)((double)(V_SIZE - 1) * smooth_d * log(smooth_d)
                                  + 0.9 * log(0.9));

        const float cross  = smooth * (sum_logp - logp_tgt) + conf * logp_tgt;
        const float kl_row = ent - cross;

        atomicAdd(out, kl_row * inv_denom);
    }
}

// ---------------------------------------------------------------------------
// z-loss: mean over rows of logsumexp(gate_logits)^2, both local and global.
// One thread per row (8 logits per row).
// ---------------------------------------------------------------------------
__global__ __launch_bounds__(THREADS)
void z_kernel(const float* __restrict__ gl_local,
              const float* __restrict__ gl_global,
              float* __restrict__ out,
              int N, float coef)   // coef = Z_COEF * 0.5 / N
{
    const int i = blockIdx.x * THREADS + threadIdx.x;
    float val = 0.0f;

    if (i < 2 * N) {
        const float* g = (i < N) ? (gl_local  + (size_t)i       * N_EXPERTS)
                                 : (gl_global + (size_t)(i - N) * N_EXPERTS);
        const float4 a = *reinterpret_cast<const float4*>(g);
        const float4 b = *reinterpret_cast<const float4*>(g + 4);
        float m = fmaxf(fmaxf(fmaxf(a.x, a.y), fmaxf(a.z, a.w)),
                        fmaxf(fmaxf(b.x, b.y), fmaxf(b.z, b.w)));
        float s = __expf(a.x - m) + __expf(a.y - m) + __expf(a.z - m) + __expf(a.w - m)
                + __expf(b.x - m) + __expf(b.y - m) + __expf(b.z - m) + __expf(b.w - m);
        const float lse = m + logf(s);
        val = lse * lse;
    }

    __shared__ float red[THREADS];
    red[threadIdx.x] = val;
    __syncthreads();
    #pragma unroll
    for (int off = THREADS / 2; off > 0; off >>= 1) {
        if (threadIdx.x < off) red[threadIdx.x] += red[threadIdx.x + off];
        __syncthreads();
    }
    if (threadIdx.x == 0) atomicAdd(out, red[0] * coef);
}

// ---------------------------------------------------------------------------
// Load-balance loss, phase 1: per-expert histograms (count, value-sum).
// 32 blocks per side; register histograms -> shared combine -> global atomics.
// ---------------------------------------------------------------------------
__global__ __launch_bounds__(THREADS)
void lb_partial_kernel(const float* __restrict__ tv_l, const int* __restrict__ ti_l,
                       const float* __restrict__ tv_g, const int* __restrict__ ti_g,
                       int N)
{
    const int side = blockIdx.x / LB_BLOCKS_PER_SIDE;        // 0 = local, 1 = global
    const int blk  = blockIdx.x % LB_BLOCKS_PER_SIDE;
    const float* tv = side ? tv_g : tv_l;
    const int*   ti = side ? ti_g : ti_l;
    const int total = N * TOPK;

    float cnt[N_EXPERTS];
    float sm [N_EXPERTS];
    #pragma unroll
    for (int j = 0; j < N_EXPERTS; j++) { cnt[j] = 0.0f; sm[j] = 0.0f; }

    const int stride = LB_BLOCKS_PER_SIDE * THREADS;
    for (int i = blk * THREADS + threadIdx.x; i < total; i += stride) {
        const int   e = ti[i];
        const float v = tv[i];
        #pragma unroll
        for (int j = 0; j < N_EXPERTS; j++) {
            const bool hit = (e == j);
            cnt[j] += hit ? 1.0f : 0.0f;
            sm[j]  += hit ? v    : 0.0f;
        }
    }

    __shared__ float s_cnt[N_EXPERTS];
    __shared__ float s_sm [N_EXPERTS];
    if (threadIdx.x < N_EXPERTS) { s_cnt[threadIdx.x] = 0.0f; s_sm[threadIdx.x] = 0.0f; }
    __syncthreads();
    #pragma unroll
    for (int j = 0; j < N_EXPERTS; j++) {
        atomicAdd(&s_cnt[j], cnt[j]);
        atomicAdd(&s_sm [j], sm[j]);
    }
    __syncthreads();

    if (threadIdx.x < N_EXPERTS) {
        atomicAdd(&g_lb_cnt[side * N_EXPERTS + threadIdx.x], s_cnt[threadIdx.x]);
        atomicAdd(&g_lb_sum[side * N_EXPERTS + threadIdx.x], s_sm[threadIdx.x]);
    }
}

// ---------------------------------------------------------------------------
// Load-balance loss, phase 2: dot products of global per-expert sums.
// ---------------------------------------------------------------------------
__global__ void lb_final_kernel(float* __restrict__ out, float coef)
{
    if (threadIdx.x == 0) {
        float acc = 0.0f;
        #pragma unroll
        for (int j = 0; j < 2 * N_EXPERTS; j++) acc += g_lb_cnt[j] * g_lb_sum[j];
        atomicAdd(out, acc * coef);
    }
}

// ---------------------------------------------------------------------------
// Launch
// ---------------------------------------------------------------------------
extern "C" void kernel_launch(void* const* d_in, const int* in_sizes, int n_in,
                              void* d_out, int out_size)
{
    const float* x    = (const float*)d_in[0];
    const int*   tgt  = (const int*)  d_in[1];
    const float* tv_l = (const float*)d_in[2];
    const int*   ti_l = (const int*)  d_in[3];
    const float* gl_l = (const float*)d_in[4];
    const float* tv_g = (const float*)d_in[5];
    const int*   ti_g = (const int*)  d_in[6];
    const float* gl_g = (const float*)d_in[7];

    float* out = (float*)d_out;

    const int N = in_sizes[1];          // B*T = 8192
    const int B = N / 1024;             // batch = 8 (denominator, NORMALIZE_LENGTH=false)

    zero_out_kernel<<<1, 32>>>(out);

    row_kernel<<<N, THREADS>>>(x, tgt, out, 1.0f / (float)B);

    const int zblocks = (2 * N + THREADS - 1) / THREADS;
    z_kernel<<<zblocks, THREADS>>>(gl_l, gl_g, out, N, 0.001f * 0.5f / (float)N);

    lb_partial_kernel<<<2 * LB_BLOCKS_PER_SIDE, THREADS>>>(tv_l, ti_l, tv_g, ti_g, N);
    lb_final_kernel<<<1, 32>>>(out, 0.01f * 0.5f * (float)N_EXPERTS / (float)N);
}

// round 5
// speedup vs baseline: 1.3912x; 1.1017x over previous
#include <cuda_runtime.h>
#include <math.h>

// Problem constants (fixed shapes for this problem instance)
#define V_SIZE    10000
#define NV4       2500          // V_SIZE / 4
#define N_EXPERTS 8
#define TOPK      2
#define THREADS   256
#define LB_BLOCKS_PER_SIDE 32
#define LB_BLOCKS (2 * LB_BLOCKS_PER_SIDE)

// Scratch for the load-balance partial sums: [side][expert]
__device__ float g_lb_cnt[2 * N_EXPERTS];
__device__ float g_lb_sum[2 * N_EXPERTS];
__device__ unsigned int g_lb_done;

// ---------------------------------------------------------------------------
// Zero the output scalar and scratch (d_out is poisoned to 0xAA).
// ---------------------------------------------------------------------------
__global__ void zero_out_kernel(float* out)
{
    if (threadIdx.x == 0) { out[0] = 0.0f; g_lb_done = 0u; }
    if (threadIdx.x < 2 * N_EXPERTS) {
        g_lb_cnt[threadIdx.x] = 0.0f;
        g_lb_sum[threadIdx.x] = 0.0f;
    }
}

// ---------------------------------------------------------------------------
// Fused kernel. Block roles by blockIdx.x:
//   [0, N)                : label-smoothing row blocks (one 40 KB row each)
//   [N, N+zblocks)        : z-loss blocks
//   [N+zblocks, +LB_BLOCKS): load-balance histogram blocks (+ last-block final)
// ---------------------------------------------------------------------------
__global__ __launch_bounds__(THREADS)
void fused_kernel(const float* __restrict__ x,
                  const int*   __restrict__ target,
                  const float* __restrict__ tv_l, const int* __restrict__ ti_l,
                  const float* __restrict__ gl_l,
                  const float* __restrict__ tv_g, const int* __restrict__ ti_g,
                  const float* __restrict__ gl_g,
                  float* __restrict__ out,
                  int N, int zblocks,
                  float inv_denom,   // 1/B
                  float z_coef,      // Z_COEF * 0.5 / N
                  float lb_coef)     // LB_COEF * 0.5 * N_EXPERTS / N
{
    const int b = blockIdx.x;
    const int t = threadIdx.x;

    // =======================================================================
    // Role 1: label-smoothing row
    // =======================================================================
    if (b < N) {
        const int row = b;
        const int tgt = target[row];
        const bool ignore = (tgt < 0);   // PADDING_IDX = -1

        const float4* __restrict__ xr =
            reinterpret_cast<const float4*>(x + (size_t)row * V_SIZE);

        float xt = 0.0f;
        if (t == 0 && !ignore) {
            xt = __ldg(x + (size_t)row * V_SIZE + (size_t)tgt);
        }

        // Per-thread online softmax over strided float4s (streaming loads).
        float m  = -3.402823466e38f;
        float s  = 0.0f;
        float sx = 0.0f;

        for (int i = t; i < NV4; i += THREADS) {
            float4 v = __ldcs(&xr[i]);
            {
                float c = v.x; sx += c;
                if (c > m) { s *= __expf(m - c); m = c; }
                s += __expf(c - m);
            }
            {
                float c = v.y; sx += c;
                if (c > m) { s *= __expf(m - c); m = c; }
                s += __expf(c - m);
            }
            {
                float c = v.z; sx += c;
                if (c > m) { s *= __expf(m - c); m = c; }
                s += __expf(c - m);
            }
            {
                float c = v.w; sx += c;
                if (c > m) { s *= __expf(m - c); m = c; }
                s += __expf(c - m);
            }
        }

        __shared__ float red_m[THREADS];
        __shared__ float red_s[THREADS];
        __shared__ float red_x[THREADS];
        red_m[t] = m; red_s[t] = s; red_x[t] = sx;
        __syncthreads();

        #pragma unroll
        for (int off = THREADS / 2; off > 0; off >>= 1) {
            if (t < off) {
                float m1 = red_m[t],       s1 = red_s[t];
                float m2 = red_m[t + off], s2 = red_s[t + off];
                float M  = fmaxf(m1, m2);
                red_s[t] = s1 * __expf(m1 - M) + s2 * __expf(m2 - M);
                red_m[t] = M;
                red_x[t] += red_x[t + off];
            }
            __syncthreads();
        }

        if (t == 0 && !ignore) {
            const float lse      = red_m[0] + logf(red_s[0]);
            const float sum_logp = red_x[0] - (float)V_SIZE * lse;
            const float logp_tgt = xt - lse;

            const float smooth = 0.1f / (float)(V_SIZE - 1);
            const float conf   = 0.9f;
            const double smooth_d = 0.1 / (double)(V_SIZE - 1);
            const float ent = (float)((double)(V_SIZE - 1) * smooth_d * log(smooth_d)
                                      + 0.9 * log(0.9));

            const float cross  = smooth * (sum_logp - logp_tgt) + conf * logp_tgt;
            const float kl_row = ent - cross;

            atomicAdd(out, kl_row * inv_denom);
        }
        return;
    }

    // =======================================================================
    // Role 2: z-loss
    // =======================================================================
    if (b < N + zblocks) {
        const int i = (b - N) * THREADS + t;
        float val = 0.0f;

        if (i < 2 * N) {
            const float* g = (i < N) ? (gl_l + (size_t)i       * N_EXPERTS)
                                     : (gl_g + (size_t)(i - N) * N_EXPERTS);
            const float4 a  = *reinterpret_cast<const float4*>(g);
            const float4 bb = *reinterpret_cast<const float4*>(g + 4);
            float m = fmaxf(fmaxf(fmaxf(a.x, a.y), fmaxf(a.z, a.w)),
                            fmaxf(fmaxf(bb.x, bb.y), fmaxf(bb.z, bb.w)));
            float s = __expf(a.x - m) + __expf(a.y - m) + __expf(a.z - m) + __expf(a.w - m)
                    + __expf(bb.x - m) + __expf(bb.y - m) + __expf(bb.z - m) + __expf(bb.w - m);
            const float lse = m + logf(s);
            val = lse * lse;
        }

        __shared__ float red[THREADS];
        red[t] = val;
        __syncthreads();
        #pragma unroll
        for (int off = THREADS / 2; off > 0; off >>= 1) {
            if (t < off) red[t] += red[t + off];
            __syncthreads();
        }
        if (t == 0) atomicAdd(out, red[0] * z_coef);
        return;
    }

    // =======================================================================
    // Role 3: load-balance histogram (+ last-block finalization)
    // =======================================================================
    {
        const int lbb  = b - N - zblocks;                   // 0..LB_BLOCKS-1
        const int side = lbb / LB_BLOCKS_PER_SIDE;          // 0 = local, 1 = global
        const int blk  = lbb % LB_BLOCKS_PER_SIDE;
        const float* tv = side ? tv_g : tv_l;
        const int*   ti = side ? ti_g : ti_l;
        const int total = N * TOPK;

        float cnt[N_EXPERTS];
        float sm [N_EXPERTS];
        #pragma unroll
        for (int j = 0; j < N_EXPERTS; j++) { cnt[j] = 0.0f; sm[j] = 0.0f; }

        const int stride = LB_BLOCKS_PER_SIDE * THREADS;
        for (int i = blk * THREADS + t; i < total; i += stride) {
            const int   e = ti[i];
            const float v = tv[i];
            #pragma unroll
            for (int j = 0; j < N_EXPERTS; j++) {
                const bool hit = (e == j);
                cnt[j] += hit ? 1.0f : 0.0f;
                sm[j]  += hit ? v    : 0.0f;
            }
        }

        __shared__ float s_cnt[N_EXPERTS];
        __shared__ float s_sm [N_EXPERTS];
        if (t < N_EXPERTS) { s_cnt[t] = 0.0f; s_sm[t] = 0.0f; }
        __syncthreads();
        #pragma unroll
        for (int j = 0; j < N_EXPERTS; j++) {
            atomicAdd(&s_cnt[j], cnt[j]);
            atomicAdd(&s_sm [j], sm[j]);
        }
        __syncthreads();

        if (t < N_EXPERTS) {
            atomicAdd(&g_lb_cnt[side * N_EXPERTS + t], s_cnt[t]);
            atomicAdd(&g_lb_sum[side * N_EXPERTS + t], s_sm[t]);
        }
        __syncthreads();

        if (t == 0) {
            __threadfence();
            const unsigned int done = atomicAdd(&g_lb_done, 1u);
            if (done == LB_BLOCKS - 1) {
                // All lb blocks' global atomics are visible.
                __threadfence();
                float acc = 0.0f;
                #pragma unroll
                for (int j = 0; j < 2 * N_EXPERTS; j++) {
                    const float c = *((volatile float*)&g_lb_cnt[j]);
                    const float v = *((volatile float*)&g_lb_sum[j]);
                    acc += c * v;
                }
                atomicAdd(out, acc * lb_coef);
            }
        }
    }
}

// ---------------------------------------------------------------------------
// Launch
// ---------------------------------------------------------------------------
extern "C" void kernel_launch(void* const* d_in, const int* in_sizes, int n_in,
                              void* d_out, int out_size)
{
    const float* x    = (const float*)d_in[0];
    const int*   tgt  = (const int*)  d_in[1];
    const float* tv_l = (const float*)d_in[2];
    const int*   ti_l = (const int*)  d_in[3];
    const float* gl_l = (const float*)d_in[4];
    const float* tv_g = (const float*)d_in[5];
    const int*   ti_g = (const int*)  d_in[6];
    const float* gl_g = (const float*)d_in[7];

    float* out = (float*)d_out;

    const int N = in_sizes[1];          // B*T = 8192
    const int B = N / 1024;             // batch = 8 (denominator, NORMALIZE_LENGTH=false)
    const int zblocks = (2 * N + THREADS - 1) / THREADS;

    zero_out_kernel<<<1, 32>>>(out);

    fused_kernel<<<N + zblocks + LB_BLOCKS, THREADS>>>(
        x, tgt, tv_l, ti_l, gl_l, tv_g, ti_g, gl_g, out,
        N, zblocks,
        1.0f / (float)B,
        0.001f * 0.5f / (float)N,
        0.01f * 0.5f * (float)N_EXPERTS / (float)N);
}